// round 13
// baseline (speedup 1.0000x reference)
#include <cuda_runtime.h>
#include <cuda_fp16.h>

// 15x15 separable Gaussian, 8192x8192 f32, reflect pad, stride 1.
// Fused separable conv (R11 base + fp16 intermediate buffer):
//   phase 1: vertical, packed f32x2 symmetric taps, register sliding window,
//            global -> smem vbuf (fp16, packed half2 stores). Interior CTAs
//            use a bumped row pointer; border CTAs use the refl path.
//   phase 2: horizontal, 8-output runs, fp32 FFMA-imm on converted fp16 window,
//            4-row interleaved task map -> conflict-free LDS.128
//            (row stride 288 B == 32 mod 128; phases hit banks {0,16,...,112}).
// fp16 intermediate adds ~3e-4 RMS rel err (tolerance 1e-3).
// Coefficients hardcoded (problem-fixed Gaussian sigma=3, 15 taps).

#define IMW 8192
#define IMH 8192
#define TX  112          // output tile width (128 vbuf cols incl. 8+8 halo)
#define TY  80           // output tile height
#define VSTRIDE_H 144    // halfs per vbuf row; 288 B, 288 % 128 == 32
#define NSX 74           // ceil(8192/112)
#define NSY 103          // ceil(8192/80)

static __device__ __forceinline__ int refl(int i) {
    i = (i < 0) ? -i : i;
    return (i >= IMW) ? (2 * IMW - 2 - i) : i;
}

__device__ __forceinline__ float2 ffma2(float2 a, float2 b, float2 c) {
    unsigned long long ua = *reinterpret_cast<unsigned long long*>(&a);
    unsigned long long ub = *reinterpret_cast<unsigned long long*>(&b);
    unsigned long long uc = *reinterpret_cast<unsigned long long*>(&c);
    unsigned long long ud;
    asm("fma.rn.f32x2 %0, %1, %2, %3;" : "=l"(ud) : "l"(ua), "l"(ub), "l"(uc));
    return *reinterpret_cast<float2*>(&ud);
}

__device__ __forceinline__ float2 fmul2(float2 a, float2 b) {
    unsigned long long ua = *reinterpret_cast<unsigned long long*>(&a);
    unsigned long long ub = *reinterpret_cast<unsigned long long*>(&b);
    unsigned long long ud;
    asm("mul.rn.f32x2 %0, %1, %2;" : "=l"(ud) : "l"(ua), "l"(ub));
    return *reinterpret_cast<float2*>(&ud);
}

__device__ __forceinline__ float2 fadd2(float2 a, float2 b) {
    unsigned long long ua = *reinterpret_cast<unsigned long long*>(&a);
    unsigned long long ub = *reinterpret_cast<unsigned long long*>(&b);
    unsigned long long ud;
    asm("add.rn.f32x2 %0, %1, %2;" : "=l"(ud) : "l"(ua), "l"(ub));
    return *reinterpret_cast<float2*>(&ud);
}

__global__ __launch_bounds__(256, 3)
void gauss_sep_kernel(const float* __restrict__ img,
                      float* __restrict__ out) {
    // normalized 1-D Gaussian, sigma=3, 15 taps (fp32)
    const float KC[15] = {
        0.00884695f, 0.01821590f, 0.03356240f, 0.05533503f,
        0.08163801f, 0.10777792f, 0.12732457f, 0.13459834f,
        0.12732457f, 0.10777792f, 0.08163801f, 0.05533503f,
        0.03356240f, 0.01821590f, 0.00884695f };

    __shared__ __align__(16) __half vbuf[TY * VSTRIDE_H];   // 23.04 KB

    const int tid = threadIdx.x;
    const int bx = blockIdx.x;
    const int by = blockIdx.y;

    // ---- phase 1: vertical conv (packed f32x2, symmetric), global -> vbuf(fp16) ----
    {
        const int pc = tid & 63;        // float2 column 0..63 (128 vbuf cols)
        const int g  = tid >> 6;        // y-group 0..3 (20 vbuf rows each)
        const int gxp = bx * TX - 8 + 2 * pc;          // global col of pair
        const int gy0 = by * TY + 20 * g;              // first output row of group

        float2 kyv[8];
        #pragma unroll
        for (int i = 0; i < 8; i++) kyv[i] = make_float2(KC[i], KC[i]);

        float2 win[15];

        const bool interior = (bx > 0) && (bx < NSX - 1) && (by > 0) && (by < NSY - 1);

        if (interior) {
            // fast path: no reflection anywhere; bumped row pointer
            const float* rp = img + (size_t)(gy0 - 7) * IMW + gxp;
            #pragma unroll
            for (int i = 0; i < 14; i++) {
                win[i] = *reinterpret_cast<const float2*>(rp);
                rp += IMW;
            }
            #pragma unroll
            for (int s = 0; s < 20; s++) {
                const float2 nv = *reinterpret_cast<const float2*>(rp);
                rp += IMW;
                win[(14 + s) % 15] = nv;

                float2 acc = fmul2(kyv[7], win[(s + 7) % 15]);
                #pragma unroll
                for (int i = 0; i < 7; i++)
                    acc = ffma2(kyv[i],
                                fadd2(win[(s + i) % 15], win[(s + 14 - i) % 15]),
                                acc);

                *reinterpret_cast<__half2*>(&vbuf[(20 * g + s) * VSTRIDE_H + 2 * pc]) =
                    __float22half2_rn(acc);
            }
        } else {
            const bool xok = (gxp >= 0) && (gxp + 1 < IMW);
            const int rx0 = refl(gxp);
            const int rx1 = refl(gxp + 1);

            #pragma unroll
            for (int i = 0; i < 14; i++) {
                const int ry = refl(gy0 - 7 + i);
                const float* rp = img + (size_t)ry * IMW;
                if (xok) {
                    win[i] = *reinterpret_cast<const float2*>(rp + gxp);
                } else {
                    win[i].x = rp[rx0]; win[i].y = rp[rx1];
                }
            }
            #pragma unroll
            for (int s = 0; s < 20; s++) {
                const int ry = refl(gy0 + s + 7);
                const float* rp = img + (size_t)ry * IMW;
                float2 nv;
                if (xok) {
                    nv = *reinterpret_cast<const float2*>(rp + gxp);
                } else {
                    nv.x = rp[rx0]; nv.y = rp[rx1];
                }
                win[(14 + s) % 15] = nv;

                float2 acc = fmul2(kyv[7], win[(s + 7) % 15]);
                #pragma unroll
                for (int i = 0; i < 7; i++)
                    acc = ffma2(kyv[i],
                                fadd2(win[(s + i) % 15], win[(s + 14 - i) % 15]),
                                acc);

                *reinterpret_cast<__half2*>(&vbuf[(20 * g + s) * VSTRIDE_H + 2 * pc]) =
                    __float22half2_rn(acc);
            }
        }
    }
    __syncthreads();

    // ---- phase 2: horizontal conv, 8-output runs, FFMA-imm, vbuf(fp16) -> out ----
    // 14 runs/row * 80 rows = 1120 tasks, 4-row interleave: addresses
    // row*32 + q*16 mod 128 -> each 8-lane LDS.128 phase hits 8 distinct banks.
    {
        const int X0  = bx * TX;
        const int gyb = by * TY;

        for (int t = tid; t < 1120; t += 256) {
            const int c   = t / 56;              // 4-row group 0..19
            const int u   = t - c * 56;
            const int row = 4 * c + (u & 3);
            const int q   = u >> 2;              // run 0..13

            const __half* vp = &vbuf[row * VSTRIDE_H + q * 8];
            // load 24 halfs = 3x LDS.128 (16B aligned), convert to fp32
            uint4 h0 = *reinterpret_cast<const uint4*>(vp);
            uint4 h1 = *reinterpret_cast<const uint4*>(vp + 8);
            uint4 h2 = *reinterpret_cast<const uint4*>(vp + 16);

            float w[24];
            {
                const unsigned hv[12] = { h0.x, h0.y, h0.z, h0.w,
                                          h1.x, h1.y, h1.z, h1.w,
                                          h2.x, h2.y, h2.z, h2.w };
                #pragma unroll
                for (int j = 0; j < 12; j++) {
                    const float2 f = __half22float2(
                        *reinterpret_cast<const __half2*>(&hv[j]));
                    w[2 * j]     = f.x;
                    w[2 * j + 1] = f.y;
                }
            }

            // output k (0..7) at tile col q*8+k uses w[1+k .. 15+k]
            float o[8];
            #pragma unroll
            for (int k = 0; k < 8; k++) o[k] = KC[0] * w[1 + k];
            #pragma unroll
            for (int i = 1; i < 15; i++) {
                #pragma unroll
                for (int k = 0; k < 8; k++)
                    o[k] = fmaf(KC[i], w[1 + k + i], o[k]);
            }

            const int gy = gyb + row;
            const int gx = X0 + 8 * q;
            if (gy < IMH && gx + 7 < IMW) {
                float* op = out + (size_t)gy * IMW + gx;
                *reinterpret_cast<float4*>(op) =
                    make_float4(o[0], o[1], o[2], o[3]);
                *reinterpret_cast<float4*>(op + 4) =
                    make_float4(o[4], o[5], o[6], o[7]);
            }
        }
    }
}

extern "C" void kernel_launch(void* const* d_in, const int* in_sizes, int n_in,
                              void* d_out, int out_size) {
    const float* img = (const float*)d_in[0];
    float* out = (float*)d_out;

    dim3 grid(NSX, NSY);
    gauss_sep_kernel<<<grid, 256>>>(img, out);
}